// round 2
// baseline (speedup 1.0000x reference)
#include <cuda_runtime.h>
#include <math.h>

// Problem constants
#define BATCH   128
#define NTOK    196
#define CDIM    768
#define NHEADS  12
#define HD      64
#define MROWS   (BATCH * NTOK)      // 25088
#define NQKV    (3 * CDIM)          // 2304
#define BHTOT   (BATCH * NHEADS)    // 1536

// Scratch (device globals: allocation-free rule)
__device__ float g_Q[BHTOT * NTOK * HD];
__device__ float g_K[BHTOT * NTOK * HD];
__device__ float g_V[BHTOT * NTOK * HD];
__device__ float g_AO[MROWS * CDIM];
__device__ float g_cos[NTOK * 32];
__device__ float g_sin[NTOK * 32];

// ---------------------------------------------------------------------------
// RoPE table: cos/sin for (t, d) with d in [0,32) (d and d+32 share values)
// ---------------------------------------------------------------------------
__global__ void rope_table_kernel() {
    int idx = blockIdx.x * blockDim.x + threadIdx.x;
    if (idx >= NTOK * 32) return;
    int t = idx / 32, dd = idx % 32;
    int y = t / 14, x = t % 14;
    float pos = (dd < 16) ? (float)y : (float)x;
    int j = (dd < 16) ? dd : dd - 16;
    // inv_freq = 10000^(-j/16)
    float invf = exp2f(-(float)j * (log2f(10000.0f) / 16.0f));
    float ang = pos * invf;
    float s, c;
    sincosf(ang, &s, &c);
    g_cos[idx] = c;
    g_sin[idx] = s;
}

// ---------------------------------------------------------------------------
// In-place RoPE rotation on a [BHTOT, NTOK, HD] tensor
// ---------------------------------------------------------------------------
__global__ void rope_apply_kernel(float* __restrict__ qk) {
    int idx = blockIdx.x * blockDim.x + threadIdx.x;   // over BHTOT*NTOK*32 pairs
    if (idx >= BHTOT * NTOK * 32) return;
    int d = idx & 31;
    int t = (idx >> 5) % NTOK;
    int bh = idx / (32 * NTOK);
    float c = g_cos[t * 32 + d];
    float s = g_sin[t * 32 + d];
    float* base = qk + ((size_t)bh * NTOK + t) * HD;
    float lo = base[d];
    float hi = base[d + 32];
    base[d]      = lo * c - hi * s;
    base[d + 32] = hi * c + lo * s;
}

// ---------------------------------------------------------------------------
// Tiled SGEMM: C[m,n] = sum_k A[m,k]*B[n,k] + bias[n]
// BM=BN=128, BK=8, 256 threads, 8x8 microtile per thread.
// mode 0: scatter into g_Q/g_K/g_V ([B,H,N,HD] layout, n -> (s,h,d))
// mode 1: write Cout[m*768 + n]
// ---------------------------------------------------------------------------
__global__ __launch_bounds__(256, 2)
void gemm128_kernel(const float* __restrict__ A, const float* __restrict__ B,
                    const float* __restrict__ bias, float* __restrict__ Cout,
                    int K, int mode) {
    __shared__ float As[8][128];
    __shared__ float Bs[8][128];

    int tid = threadIdx.x;
    int bm = blockIdx.y, bn = blockIdx.x;
    int lrow = tid >> 1;
    int lk   = (tid & 1) * 4;

    const float* Aptr = A + ((size_t)(bm * 128 + lrow)) * K + lk;
    const float* Bptr = B + ((size_t)(bn * 128 + lrow)) * K + lk;

    int ty = tid >> 4, tx = tid & 15;
    float acc[8][8];
#pragma unroll
    for (int i = 0; i < 8; i++)
#pragma unroll
        for (int j = 0; j < 8; j++) acc[i][j] = 0.0f;

    for (int k0 = 0; k0 < K; k0 += 8) {
        float4 a4 = *(const float4*)(Aptr + k0);
        float4 b4 = *(const float4*)(Bptr + k0);
        __syncthreads();
        As[lk + 0][lrow] = a4.x; As[lk + 1][lrow] = a4.y;
        As[lk + 2][lrow] = a4.z; As[lk + 3][lrow] = a4.w;
        Bs[lk + 0][lrow] = b4.x; Bs[lk + 1][lrow] = b4.y;
        Bs[lk + 2][lrow] = b4.z; Bs[lk + 3][lrow] = b4.w;
        __syncthreads();
#pragma unroll
        for (int kk = 0; kk < 8; kk++) {
            float4 a0 = *(const float4*)&As[kk][ty * 8];
            float4 a1 = *(const float4*)&As[kk][ty * 8 + 4];
            float4 b0 = *(const float4*)&Bs[kk][tx * 8];
            float4 b1 = *(const float4*)&Bs[kk][tx * 8 + 4];
            float ar[8] = {a0.x, a0.y, a0.z, a0.w, a1.x, a1.y, a1.z, a1.w};
            float br[8] = {b0.x, b0.y, b0.z, b0.w, b1.x, b1.y, b1.z, b1.w};
#pragma unroll
            for (int i = 0; i < 8; i++)
#pragma unroll
                for (int j = 0; j < 8; j++)
                    acc[i][j] += ar[i] * br[j];
        }
    }

    if (mode == 0) {
#pragma unroll
        for (int i = 0; i < 8; i++) {
            int m = bm * 128 + ty * 8 + i;
            int b = m / NTOK, t = m % NTOK;
#pragma unroll
            for (int j = 0; j < 8; j++) {
                int n = bn * 128 + tx * 8 + j;
                float v = acc[i][j] + bias[n];
                int s = n / CDIM;
                int r = n % CDIM;
                int h = r >> 6, d = r & 63;
                size_t off = (((size_t)(b * NHEADS + h)) * NTOK + t) * HD + d;
                float* dst = (s == 0) ? g_Q : (s == 1) ? g_K : g_V;
                dst[off] = v;
            }
        }
    } else {
#pragma unroll
        for (int i = 0; i < 8; i++) {
            int m = bm * 128 + ty * 8 + i;
#pragma unroll
            for (int j = 0; j < 8; j++) {
                int n = bn * 128 + tx * 8 + j;
                Cout[(size_t)m * CDIM + n] = acc[i][j] + bias[n];
            }
        }
    }
}

// ---------------------------------------------------------------------------
// Attention: one block per (b,h). Kt [64][196] + V [196][64] resident in smem.
// Per-warp row processing: scores -> softmax -> P@V. Writes AO in [B,N,C].
// ---------------------------------------------------------------------------
#define ATT_SMEM_FLOATS (64 * NTOK + NTOK * 64 + 8 * 64 + 8 * NTOK)

__global__ void attention_kernel(float* __restrict__ AO) {
    extern __shared__ float sm[];
    float* Kt   = sm;                         // [64][196]
    float* Vs   = Kt + 64 * NTOK;             // [196][64]
    float* Qrow = Vs + NTOK * 64;             // [8][64]
    float* P    = Qrow + 8 * 64;              // [8][196]

    int bh = blockIdx.x;
    int b = bh / NHEADS, h = bh % NHEADS;
    int tid = threadIdx.x, warp = tid >> 5, lane = tid & 31;

    const float* Qg = g_Q + (size_t)bh * NTOK * HD;
    const float* Kg = g_K + (size_t)bh * NTOK * HD;
    const float* Vg = g_V + (size_t)bh * NTOK * HD;

    for (int i = tid; i < NTOK * HD; i += 256) {
        int j = i >> 6, d = i & 63;
        Kt[d * NTOK + j] = Kg[i];
        Vs[i] = Vg[i];
    }
    __syncthreads();

    const float scale = 0.125f;   // 64^-0.5

    for (int r = warp; r < NTOK; r += 8) {
        Qrow[warp * 64 + lane]      = Qg[r * HD + lane];
        Qrow[warp * 64 + lane + 32] = Qg[r * HD + lane + 32];
        __syncwarp();

        float sv[7];
        float mloc = -1e30f;
        int cnt = 0;
        for (int j = lane; j < NTOK; j += 32) {
            float acc = 0.0f;
#pragma unroll
            for (int i = 0; i < HD; i++)
                acc += Qrow[warp * 64 + i] * Kt[i * NTOK + j];
            acc *= scale;
            sv[cnt++] = acc;
            mloc = fmaxf(mloc, acc);
        }
#pragma unroll
        for (int o = 16; o; o >>= 1)
            mloc = fmaxf(mloc, __shfl_xor_sync(0xFFFFFFFFu, mloc, o));

        float zloc = 0.0f;
        cnt = 0;
        for (int j = lane; j < NTOK; j += 32) {
            float e = __expf(sv[cnt++] - mloc);
            P[warp * NTOK + j] = e;
            zloc += e;
        }
#pragma unroll
        for (int o = 16; o; o >>= 1)
            zloc += __shfl_xor_sync(0xFFFFFFFFu, zloc, o);
        float inv = 1.0f / zloc;
        __syncwarp();

#pragma unroll
        for (int dblk = 0; dblk < 2; dblk++) {
            int d = lane + dblk * 32;
            float acc = 0.0f;
            for (int j = 0; j < NTOK; j++)
                acc += P[warp * NTOK + j] * Vs[j * 64 + d];
            AO[((size_t)b * NTOK + r) * CDIM + h * 64 + d] = acc * inv;
        }
        __syncwarp();
    }
}

// ---------------------------------------------------------------------------
extern "C" void kernel_launch(void* const* d_in, const int* in_sizes, int n_in,
                              void* d_out, int out_size) {
    const float* x      = (const float*)d_in[0];
    const float* qkv_w  = (const float*)d_in[1];
    const float* qkv_b  = (const float*)d_in[2];
    const float* proj_w = (const float*)d_in[3];
    const float* proj_b = (const float*)d_in[4];
    float* out = (float*)d_out;

    // 1. RoPE tables
    rope_table_kernel<<<(NTOK * 32 + 255) / 256, 256>>>();

    // 2. QKV GEMM + scatter to [B,H,N,HD]
    {
        dim3 grid(NQKV / 128, MROWS / 128);   // (18, 196)
        gemm128_kernel<<<grid, 256>>>(x, qkv_w, qkv_b, nullptr, CDIM, 0);
    }

    // 3. RoPE on Q and K
    {
        int total = BHTOT * NTOK * 32;
        int blocks = (total + 255) / 256;
        float* qptr; cudaGetSymbolAddress((void**)&qptr, g_Q);
        float* kptr; cudaGetSymbolAddress((void**)&kptr, g_K);
        rope_apply_kernel<<<blocks, 256>>>(qptr);
        rope_apply_kernel<<<blocks, 256>>>(kptr);
    }

    // 4. Attention
    {
        float* aoptr; cudaGetSymbolAddress((void**)&aoptr, g_AO);
        int smem = ATT_SMEM_FLOATS * sizeof(float);   // ~106 KB
        static bool attr_set = false;
        cudaFuncSetAttribute(attention_kernel,
                             cudaFuncAttributeMaxDynamicSharedMemorySize, smem);
        (void)attr_set;
        attention_kernel<<<BHTOT, 256, smem>>>(aoptr);
    }

    // 5. Output projection
    {
        float* aoptr; cudaGetSymbolAddress((void**)&aoptr, g_AO);
        dim3 grid(CDIM / 128, MROWS / 128);   // (6, 196)
        gemm128_kernel<<<grid, 256>>>(aoptr, proj_w, proj_b, out, CDIM, 1);
    }
}

// round 5
// speedup vs baseline: 1.0434x; 1.0434x over previous
#include <cuda_runtime.h>
#include <math.h>

// Problem constants
#define BATCH   128
#define NTOK    196
#define CDIM    768
#define NHEADS  12
#define HD      64
#define MROWS   (BATCH * NTOK)      // 25088
#define NQKV    (3 * CDIM)          // 2304
#define BHTOT   (BATCH * NHEADS)    // 1536
#define BK      16

// Scratch (device globals: allocation-free rule)
__device__ float g_Q[BHTOT * NTOK * HD];
__device__ float g_K[BHTOT * NTOK * HD];
__device__ float g_V[BHTOT * NTOK * HD];
__device__ float g_AO[MROWS * CDIM];
__device__ float g_cos[NTOK * 32];
__device__ float g_sin[NTOK * 32];

typedef unsigned long long u64;

__device__ __forceinline__ u64 pack2(float lo, float hi) {
    u64 r; asm("mov.b64 %0,{%1,%2};" : "=l"(r) : "f"(lo), "f"(hi)); return r;
}
__device__ __forceinline__ void unpack2(u64 v, float &lo, float &hi) {
    asm("mov.b64 {%0,%1},%2;" : "=f"(lo), "=f"(hi) : "l"(v));
}
__device__ __forceinline__ void fma2(u64 &d, u64 a, u64 b) {
    asm("fma.rn.f32x2 %0,%1,%2,%3;" : "=l"(d) : "l"(a), "l"(b), "l"(d));
}

// ---------------------------------------------------------------------------
// RoPE table: cos/sin for (t, d) with d in [0,32)
// ---------------------------------------------------------------------------
__global__ void rope_table_kernel() {
    int idx = blockIdx.x * blockDim.x + threadIdx.x;
    if (idx >= NTOK * 32) return;
    int t = idx / 32, dd = idx % 32;
    int y = t / 14, x = t % 14;
    float pos = (dd < 16) ? (float)y : (float)x;
    int j = (dd < 16) ? dd : dd - 16;
    float invf = exp2f(-(float)j * (log2f(10000.0f) / 16.0f));
    float ang = pos * invf;
    float s, c;
    sincosf(ang, &s, &c);
    g_cos[idx] = c;
    g_sin[idx] = s;
}

// ---------------------------------------------------------------------------
// f32x2 tiled SGEMM: C[m,n] = sum_k A[m,k]*B[n,k] + bias[n]
// BM=BN=128, BK=16, 256 threads, 8x8 microtile via FFMA2 pairs.
// Column mapping per thread: n = bn*128 + 32*j + 2*tx + p  (j=0..3, p=0..1)
// mode 0: scatter into g_Q/g_K/g_V with fused RoPE on Q,K
// mode 1: write Cout[m*768 + n]
// ---------------------------------------------------------------------------
__global__ __launch_bounds__(256, 2)
void gemm_f32x2_kernel(const float* __restrict__ A, const float* __restrict__ B,
                       const float* __restrict__ bias, float* __restrict__ Cout,
                       int K, int mode) {
    __shared__ float As[BK][256];   // m-duplicated: As[k][2m]==As[k][2m+1]
    __shared__ float Bs[BK][128];

    int tid = threadIdx.x;
    int bm = blockIdx.y, bn = blockIdx.x;
    int lrow = tid >> 1;
    int lk   = (tid & 1) * 8;

    const float* Aptr = A + ((size_t)(bm * 128 + lrow)) * K + lk;
    const float* Bptr = B + ((size_t)(bn * 128 + lrow)) * K + lk;

    int ty = tid >> 4, tx = tid & 15;

    u64 acc[8][4];
#pragma unroll
    for (int i = 0; i < 8; i++)
#pragma unroll
        for (int j = 0; j < 4; j++) acc[i][j] = 0ull;

    // prefetch first tile
    float4 a0 = *(const float4*)(Aptr);
    float4 a1 = *(const float4*)(Aptr + 4);
    float4 b0 = *(const float4*)(Bptr);
    float4 b1 = *(const float4*)(Bptr + 4);

    for (int k0 = 0; k0 < K; k0 += BK) {
        __syncthreads();
        // store A duplicated (u64 = {v,v}), B plain
        {
            float av[8] = {a0.x, a0.y, a0.z, a0.w, a1.x, a1.y, a1.z, a1.w};
            float bv[8] = {b0.x, b0.y, b0.z, b0.w, b1.x, b1.y, b1.z, b1.w};
#pragma unroll
            for (int q = 0; q < 8; q++) {
                *(u64*)&As[lk + q][2 * lrow] = pack2(av[q], av[q]);
                Bs[lk + q][lrow] = bv[q];
            }
        }
        __syncthreads();
        // prefetch next tile while computing
        if (k0 + BK < K) {
            a0 = *(const float4*)(Aptr + k0 + BK);
            a1 = *(const float4*)(Aptr + k0 + BK + 4);
            b0 = *(const float4*)(Bptr + k0 + BK);
            b1 = *(const float4*)(Bptr + k0 + BK + 4);
        }
#pragma unroll
        for (int kk = 0; kk < BK; kk++) {
            u64 aa[8];
#pragma unroll
            for (int ii = 0; ii < 4; ii++) {
                ulonglong2 t2 = *(const ulonglong2*)&As[kk][ty * 16 + ii * 4];
                aa[2 * ii] = t2.x; aa[2 * ii + 1] = t2.y;
            }
            u64 bb[4];
#pragma unroll
            for (int j = 0; j < 4; j++)
                bb[j] = *(const u64*)&Bs[kk][2 * tx + 32 * j];
#pragma unroll
            for (int i = 0; i < 8; i++)
#pragma unroll
                for (int j = 0; j < 4; j++)
                    fma2(acc[i][j], aa[i], bb[j]);
        }
    }

    if (mode == 0) {
        // scatter to Q/K/V with fused RoPE. Thread holds (d, d+32) pairs:
        // j and j+1 (j even) are n and n+32 of the same head.
#pragma unroll
        for (int i = 0; i < 8; i++) {
            int m = bm * 128 + ty * 8 + i;
            int b = m / NTOK, t = m % NTOK;
#pragma unroll
            for (int jh = 0; jh < 2; jh++) {
                float vA0, vA1, vB0, vB1;
                unpack2(acc[i][2 * jh],     vA0, vA1);
                unpack2(acc[i][2 * jh + 1], vB0, vB1);
                int nlo = bn * 128 + 64 * jh + 2 * tx;
#pragma unroll
                for (int p = 0; p < 2; p++) {
                    int n = nlo + p;
                    float lo = (p ? vA1 : vA0) + bias[n];
                    float hi = (p ? vB1 : vB0) + bias[n + 32];
                    int s = n / CDIM;
                    int r = n % CDIM;
                    int h = r >> 6, d = r & 63;   // d < 32 by construction
                    float* dst = (s == 0) ? g_Q : (s == 1) ? g_K : g_V;
                    size_t off = (((size_t)(b * NHEADS + h)) * NTOK + t) * HD;
                    if (s < 2) {
                        float c  = g_cos[t * 32 + d];
                        float sn = g_sin[t * 32 + d];
                        dst[off + d]      = lo * c - hi * sn;
                        dst[off + d + 32] = hi * c + lo * sn;
                    } else {
                        dst[off + d]      = lo;
                        dst[off + d + 32] = hi;
                    }
                }
            }
        }
    } else {
#pragma unroll
        for (int i = 0; i < 8; i++) {
            int m = bm * 128 + ty * 8 + i;
#pragma unroll
            for (int j = 0; j < 4; j++) {
                int n = bn * 128 + 32 * j + 2 * tx;
                float v0, v1;
                unpack2(acc[i][j], v0, v1);
                float2 w = make_float2(v0 + bias[n], v1 + bias[n + 1]);
                *(float2*)&Cout[(size_t)m * CDIM + n] = w;
            }
        }
    }
}

// ---------------------------------------------------------------------------
// Attention: one block per (b,h). Kt [64][196] + V [196][64] resident in smem.
// ---------------------------------------------------------------------------
#define ATT_SMEM_FLOATS (64 * NTOK + NTOK * 64 + 8 * 64 + 8 * NTOK)

__global__ void attention_kernel(float* __restrict__ AO) {
    extern __shared__ float sm[];
    float* Kt   = sm;                         // [64][196]
    float* Vs   = Kt + 64 * NTOK;             // [196][64]
    float* Qrow = Vs + NTOK * 64;             // [8][64]
    float* P    = Qrow + 8 * 64;              // [8][196]

    int bh = blockIdx.x;
    int b = bh / NHEADS, h = bh % NHEADS;
    int tid = threadIdx.x, warp = tid >> 5, lane = tid & 31;

    const float* Qg = g_Q + (size_t)bh * NTOK * HD;
    const float* Kg = g_K + (size_t)bh * NTOK * HD;
    const float* Vg = g_V + (size_t)bh * NTOK * HD;

    for (int i = tid; i < NTOK * HD; i += 256) {
        int j = i >> 6, d = i & 63;
        Kt[d * NTOK + j] = Kg[i];
        Vs[i] = Vg[i];
    }
    __syncthreads();

    const float scale = 0.125f;   // 64^-0.5

    for (int r = warp; r < NTOK; r += 8) {
        Qrow[warp * 64 + lane]      = Qg[r * HD + lane];
        Qrow[warp * 64 + lane + 32] = Qg[r * HD + lane + 32];
        __syncwarp();

        float sv[7];
        float mloc = -1e30f;
        int cnt = 0;
        for (int j = lane; j < NTOK; j += 32) {
            float acc = 0.0f;
#pragma unroll
            for (int i = 0; i < HD; i++)
                acc += Qrow[warp * 64 + i] * Kt[i * NTOK + j];
            acc *= scale;
            sv[cnt++] = acc;
            mloc = fmaxf(mloc, acc);
        }
#pragma unroll
        for (int o = 16; o; o >>= 1)
            mloc = fmaxf(mloc, __shfl_xor_sync(0xFFFFFFFFu, mloc, o));

        float zloc = 0.0f;
        cnt = 0;
        for (int j = lane; j < NTOK; j += 32) {
            float e = __expf(sv[cnt++] - mloc);
            P[warp * NTOK + j] = e;
            zloc += e;
        }
#pragma unroll
        for (int o = 16; o; o >>= 1)
            zloc += __shfl_xor_sync(0xFFFFFFFFu, zloc, o);
        float inv = 1.0f / zloc;
        __syncwarp();

#pragma unroll
        for (int dblk = 0; dblk < 2; dblk++) {
            int d = lane + dblk * 32;
            float acc = 0.0f;
            for (int j = 0; j < NTOK; j++)
                acc += P[warp * NTOK + j] * Vs[j * 64 + d];
            AO[((size_t)b * NTOK + r) * CDIM + h * 64 + d] = acc * inv;
        }
        __syncwarp();
    }
}

// ---------------------------------------------------------------------------
extern "C" void kernel_launch(void* const* d_in, const int* in_sizes, int n_in,
                              void* d_out, int out_size) {
    const float* x      = (const float*)d_in[0];
    const float* qkv_w  = (const float*)d_in[1];
    const float* qkv_b  = (const float*)d_in[2];
    const float* proj_w = (const float*)d_in[3];
    const float* proj_b = (const float*)d_in[4];
    float* out = (float*)d_out;

    // 1. RoPE tables (needed by the QKV epilogue)
    rope_table_kernel<<<(NTOK * 32 + 255) / 256, 256>>>();

    // 2. QKV GEMM + fused RoPE + scatter to [B,H,N,HD]
    {
        dim3 grid(NQKV / 128, MROWS / 128);   // (18, 196)
        gemm_f32x2_kernel<<<grid, 256>>>(x, qkv_w, qkv_b, nullptr, CDIM, 0);
    }

    // 3. Attention
    {
        float* aoptr; cudaGetSymbolAddress((void**)&aoptr, g_AO);
        int smem = ATT_SMEM_FLOATS * sizeof(float);   // ~106 KB
        cudaFuncSetAttribute(attention_kernel,
                             cudaFuncAttributeMaxDynamicSharedMemorySize, smem);
        attention_kernel<<<BHTOT, 256, smem>>>(aoptr);
    }

    // 4. Output projection
    {
        float* aoptr; cudaGetSymbolAddress((void**)&aoptr, g_AO);
        dim3 grid(CDIM / 128, MROWS / 128);   // (6, 196)
        gemm_f32x2_kernel<<<grid, 256>>>(aoptr, proj_w, proj_b, out, CDIM, 1);
    }
}